// round 3
// baseline (speedup 1.0000x reference)
#include <cuda_runtime.h>
#include <math.h>

// ---------------------------------------------------------------------------
// Problem constants
// ---------------------------------------------------------------------------
namespace {
constexpr int Bb = 8;
constexpr int Hh = 4;
constexpr int Nn = 1024;
constexpr int KV = 960;
constexpr int CMAX = 512;
}

// ---------------------------------------------------------------------------
// Scratch (static device globals — allocation-free per harness rules)
// ---------------------------------------------------------------------------
__device__ float g_K[(size_t)Bb * Hh * Nn * KV];     // [b,h,n,kv]
__device__ float g_V[(size_t)Bb * Hh * Nn * KV];     // [b,h,n,kv]
__device__ float g_Q[(size_t)Bb * Hh * Nn * CMAX];   // [b,h,n,c]
__device__ float g_S[(size_t)Bb * Hh * CMAX * KV];   // [b,h,c,kv]
__device__ float g_ctx[(size_t)Bb * Nn * CMAX];      // [b,n,c]
__device__ float g_stats[Bb * Hh * 2];               // mean, inv per (b,h)

// ---------------------------------------------------------------------------
// Tiled SGEMM, 128x128x8 tile, 8x8 per thread, 256 threads
// ---------------------------------------------------------------------------
#define TBM 128
#define TBN 128
#define TBK 8

// C[z][m][n] = scale * sum_h sum_k A_h[m][k] * B_h[n][k]    ("NT": both row-major [*,K])
__global__ __launch_bounds__(256, 2)
void gemm_nt(const float* __restrict__ A, const float* __restrict__ B,
             float* __restrict__ C,
             int M, int N, int K,
             long sAo, long sAi, long sBo, long sBi, long sC,
             int hDiv, int nAcc, long accA, long accB, float scale)
{
    __shared__ __align__(16) float As[TBK][TBM];
    __shared__ __align__(16) float Bs[TBK][TBN];

    const int tid = threadIdx.x;
    const int m0 = blockIdx.y * TBM;
    const int n0 = blockIdx.x * TBN;
    const int z  = blockIdx.z;

    const float* Abase = A + (long)(z / hDiv) * sAo + (long)(z % hDiv) * sAi;
    const float* Bbase = B + (long)(z / hDiv) * sBo + (long)(z % hDiv) * sBi;
    float* Cp = C + (long)z * sC;

    float acc[8][8];
#pragma unroll
    for (int i = 0; i < 8; i++)
#pragma unroll
        for (int j = 0; j < 8; j++) acc[i][j] = 0.f;

    const int lr = tid >> 1;          // 0..127 : tile row
    const int ls = (tid & 1) * 4;     // 0 or 4 : k quad
    const int ty = tid >> 4;
    const int tx = tid & 15;

    for (int h = 0; h < nAcc; ++h) {
        const float* Ah = Abase + (long)h * accA;
        const float* Bh = Bbase + (long)h * accB;
        for (int k0 = 0; k0 < K; k0 += TBK) {
            float4 va = make_float4(0.f, 0.f, 0.f, 0.f);
            float4 vb = make_float4(0.f, 0.f, 0.f, 0.f);
            const int ma = m0 + lr;
            const int nb = n0 + lr;
            if (ma < M) va = *reinterpret_cast<const float4*>(Ah + (long)ma * K + k0 + ls);
            if (nb < N) vb = *reinterpret_cast<const float4*>(Bh + (long)nb * K + k0 + ls);
            As[ls + 0][lr] = va.x; As[ls + 1][lr] = va.y;
            As[ls + 2][lr] = va.z; As[ls + 3][lr] = va.w;
            Bs[ls + 0][lr] = vb.x; Bs[ls + 1][lr] = vb.y;
            Bs[ls + 2][lr] = vb.z; Bs[ls + 3][lr] = vb.w;
            __syncthreads();
#pragma unroll
            for (int kk = 0; kk < TBK; ++kk) {
                float a[8], b[8];
#pragma unroll
                for (int i = 0; i < 8; i++) a[i] = As[kk][ty * 8 + i];
#pragma unroll
                for (int j = 0; j < 8; j++) b[j] = Bs[kk][tx * 8 + j];
#pragma unroll
                for (int i = 0; i < 8; i++)
#pragma unroll
                    for (int j = 0; j < 8; j++) acc[i][j] += a[i] * b[j];
            }
            __syncthreads();
        }
    }
#pragma unroll
    for (int i = 0; i < 8; i++) {
        const int m = m0 + ty * 8 + i;
        if (m >= M) continue;
#pragma unroll
        for (int j = 0; j < 8; j++) {
            const int n = n0 + tx * 8 + j;
            if (n < N) Cp[(long)m * N + n] = acc[i][j] * scale;
        }
    }
}

// C[z][m][n] = scale * sum_k A[k][m] * B[k][n]   ("TN": A row-major [K,M], B row-major [K,N])
__global__ __launch_bounds__(256, 2)
void gemm_tn(const float* __restrict__ A, const float* __restrict__ B,
             float* __restrict__ C,
             int M, int N, int K,
             long sA, long sB, long sC, float scale)
{
    __shared__ __align__(16) float As[TBK][TBM];
    __shared__ __align__(16) float Bs[TBK][TBN];

    const int tid = threadIdx.x;
    const int m0 = blockIdx.y * TBM;
    const int n0 = blockIdx.x * TBN;
    const int z  = blockIdx.z;

    const float* Ah = A + (long)z * sA;
    const float* Bh = B + (long)z * sB;
    float* Cp = C + (long)z * sC;

    float acc[8][8];
#pragma unroll
    for (int i = 0; i < 8; i++)
#pragma unroll
        for (int j = 0; j < 8; j++) acc[i][j] = 0.f;

    const int kr = tid >> 5;            // 0..7
    const int mc = (tid & 31) * 4;      // 0..124
    const int ty = tid >> 4;
    const int tx = tid & 15;

    for (int k0 = 0; k0 < K; k0 += TBK) {
        float4 va = make_float4(0.f, 0.f, 0.f, 0.f);
        float4 vb = make_float4(0.f, 0.f, 0.f, 0.f);
        const int m = m0 + mc;
        const int n = n0 + mc;
        if (m < M) va = *reinterpret_cast<const float4*>(Ah + (long)(k0 + kr) * M + m);
        if (n < N) vb = *reinterpret_cast<const float4*>(Bh + (long)(k0 + kr) * N + n);
        *reinterpret_cast<float4*>(&As[kr][mc]) = va;
        *reinterpret_cast<float4*>(&Bs[kr][mc]) = vb;
        __syncthreads();
#pragma unroll
        for (int kk = 0; kk < TBK; ++kk) {
            float a[8], b[8];
#pragma unroll
            for (int i = 0; i < 8; i++) a[i] = As[kk][ty * 8 + i];
#pragma unroll
            for (int j = 0; j < 8; j++) b[j] = Bs[kk][tx * 8 + j];
#pragma unroll
            for (int i = 0; i < 8; i++)
#pragma unroll
                for (int j = 0; j < 8; j++) acc[i][j] += a[i] * b[j];
        }
        __syncthreads();
    }
#pragma unroll
    for (int i = 0; i < 8; i++) {
        const int m = m0 + ty * 8 + i;
        if (m >= M) continue;
#pragma unroll
        for (int j = 0; j < 8; j++) {
            const int n = n0 + tx * 8 + j;
            if (n < N) Cp[(long)m * N + n] = acc[i][j] * scale;
        }
    }
}

// ---------------------------------------------------------------------------
// Instance-norm statistics: per (b,h) -> mean, rsqrt(var+eps) over C*KV elems
// ---------------------------------------------------------------------------
__inline__ __device__ float warpSum(float v) {
#pragma unroll
    for (int o = 16; o; o >>= 1) v += __shfl_xor_sync(0xffffffffu, v, o);
    return v;
}
__inline__ __device__ float warpMax(float v) {
#pragma unroll
    for (int o = 16; o; o >>= 1) v = fmaxf(v, __shfl_xor_sync(0xffffffffu, v, o));
    return v;
}

__global__ void stats_kernel(const float* __restrict__ S, float* __restrict__ stats, int C)
{
    const int z = blockIdx.x;
    const long n = (long)C * KV;
    const float* p = S + (long)z * n;
    float s = 0.f, sq = 0.f;
    for (long i = threadIdx.x; i < n; i += blockDim.x) {
        const float x = p[i];
        s += x;
        sq += x * x;
    }
    __shared__ float sh1[16], sh2[16];
    s = warpSum(s);
    sq = warpSum(sq);
    const int w = threadIdx.x >> 5, l = threadIdx.x & 31;
    if (l == 0) { sh1[w] = s; sh2[w] = sq; }
    __syncthreads();
    if (w == 0) {
        s  = (l < 16) ? sh1[l] : 0.f;
        sq = (l < 16) ? sh2[l] : 0.f;
        s = warpSum(s);
        sq = warpSum(sq);
        if (l == 0) {
            const float invn = 1.f / (float)n;
            const float mean = s * invn;
            const float var  = sq * invn - mean * mean;  // biased, matches jnp.var
            stats[z * 2 + 0] = mean;
            stats[z * 2 + 1] = rsqrtf(var + 1e-5f);
        }
    }
}

// ---------------------------------------------------------------------------
// Softmax over KV axis (instance-norm mean cancels; only inv scaling matters)
// ---------------------------------------------------------------------------
__global__ void softmax_kernel(float* __restrict__ S, const float* __restrict__ stats, int C)
{
    const int row = blockIdx.x;            // 0 .. 32*C-1
    const int z = row / C;
    const float inv = stats[z * 2 + 1];
    float* p = S + (long)row * KV;
    const int tid = threadIdx.x;
    const int w = tid >> 5, l = tid & 31;

    __shared__ float sred[8];
    __shared__ float s_mx, s_se;

    float mx = -1e30f;
    for (int i = tid; i < KV; i += 256) mx = fmaxf(mx, p[i]);
    mx = warpMax(mx);
    if (l == 0) sred[w] = mx;
    __syncthreads();
    if (tid == 0) {
        float m = sred[0];
#pragma unroll
        for (int i = 1; i < 8; i++) m = fmaxf(m, sred[i]);
        s_mx = m;
    }
    __syncthreads();
    mx = s_mx;

    float se = 0.f;
    for (int i = tid; i < KV; i += 256) {
        const float e = expf((p[i] - mx) * inv);
        p[i] = e;
        se += e;
    }
    se = warpSum(se);
    __syncthreads();
    if (l == 0) sred[w] = se;
    __syncthreads();
    if (tid == 0) {
        float t = 0.f;
#pragma unroll
        for (int i = 0; i < 8; i++) t += sred[i];
        s_se = 1.f / t;
    }
    __syncthreads();
    const float r = s_se;
    for (int i = tid; i < KV; i += 256) p[i] *= r;
}

// ---------------------------------------------------------------------------
// Host launch — input-order detection; dict order has Wq/Wo INTERLEAVED
// (setup_inputs builds Wq_i and Wo_i inside one loop).
// ---------------------------------------------------------------------------
extern "C" void kernel_launch(void* const* d_in, const int* in_sizes, int n_in,
                              void* d_out, int out_size)
{
    (void)n_in; (void)out_size;

    int ie[4], ieall, iwq[4], iwo[4], iwk, iwv;

    const int SZ_WK   = 4 * 960 * 960;     // 3,686,400
    const int SZ_EMB1 = 8 * 1024 * 64;     //   524,288
    const int SZ_WO1  = 64 * 64;           //     4,096

    if (in_sizes[0] == SZ_WK) {
        // ASCII-sorted: Wk, Wo1..4, Wq1..4, Wv, emb1..4, emb_all
        iwk = 0;
        iwo[0] = 1; iwo[1] = 2; iwo[2] = 3; iwo[3] = 4;
        iwq[0] = 5; iwq[1] = 6; iwq[2] = 7; iwq[3] = 8;
        iwv = 9;
        ie[0] = 10; ie[1] = 11; ie[2] = 12; ie[3] = 13;
        ieall = 14;
    } else if (in_sizes[0] == SZ_EMB1 && in_sizes[5] == SZ_WK) {
        // lowercase-sorted: emb1..4, emb_all, wk, wo1..4, wq1..4, wv
        ie[0] = 0; ie[1] = 1; ie[2] = 2; ie[3] = 3;
        ieall = 4;
        iwk = 5;
        iwo[0] = 6; iwo[1] = 7; iwo[2] = 8; iwo[3] = 9;
        iwq[0] = 10; iwq[1] = 11; iwq[2] = 12; iwq[3] = 13;
        iwv = 14;
    } else if (in_sizes[6] == SZ_WO1) {
        // dict insertion order (INTERLEAVED): emb1..4, emb_all,
        //   Wq1, Wo1, Wq2, Wo2, Wq3, Wo3, Wq4, Wo4, Wk, Wv
        ie[0] = 0; ie[1] = 1; ie[2] = 2; ie[3] = 3;
        ieall = 4;
        iwq[0] = 5;  iwo[0] = 6;
        iwq[1] = 7;  iwo[1] = 8;
        iwq[2] = 9;  iwo[2] = 10;
        iwq[3] = 11; iwo[3] = 12;
        iwk = 13;
        iwv = 14;
    } else {
        // sequential fallback: emb1..4, emb_all, Wq1..4, Wo1..4, Wk, Wv
        ie[0] = 0; ie[1] = 1; ie[2] = 2; ie[3] = 3;
        ieall = 4;
        iwq[0] = 5; iwq[1] = 6; iwq[2] = 7; iwq[3] = 8;
        iwo[0] = 9; iwo[1] = 10; iwo[2] = 11; iwo[3] = 12;
        iwk = 13;
        iwv = 14;
    }

    const float* emb[4]  = {(const float*)d_in[ie[0]], (const float*)d_in[ie[1]],
                            (const float*)d_in[ie[2]], (const float*)d_in[ie[3]]};
    const float* emb_all = (const float*)d_in[ieall];
    const float* Wq[4]   = {(const float*)d_in[iwq[0]], (const float*)d_in[iwq[1]],
                            (const float*)d_in[iwq[2]], (const float*)d_in[iwq[3]]};
    const float* Wo[4]   = {(const float*)d_in[iwo[0]], (const float*)d_in[iwo[1]],
                            (const float*)d_in[iwo[2]], (const float*)d_in[iwo[3]]};
    const float* Wk      = (const float*)d_in[iwk];
    const float* Wv      = (const float*)d_in[iwv];
    float* out = (float*)d_out;

    float *pK, *pV, *pQ, *pS, *pC, *pSt;
    cudaGetSymbolAddress((void**)&pK, g_K);
    cudaGetSymbolAddress((void**)&pV, g_V);
    cudaGetSymbolAddress((void**)&pQ, g_Q);
    cudaGetSymbolAddress((void**)&pS, g_S);
    cudaGetSymbolAddress((void**)&pC, g_ctx);
    cudaGetSymbolAddress((void**)&pSt, g_stats);

    const int Cs[4] = {64, 128, 256, 512};
    const float sscale = 0.032274861f;  // 1/sqrt(960)
    const dim3 blk(256);

    // K = emb_all @ Wk[h]^T   per (b,h)
    gemm_nt<<<dim3(8, 8, Bb * Hh), blk>>>(
        emb_all, Wk, pK, Nn, KV, KV,
        (long)Nn * KV, 0, 0, (long)KV * KV, (long)Nn * KV,
        Hh, 1, 0, 0, 1.f);
    // V = emb_all @ Wv[h]^T
    gemm_nt<<<dim3(8, 8, Bb * Hh), blk>>>(
        emb_all, Wv, pV, Nn, KV, KV,
        (long)Nn * KV, 0, 0, (long)KV * KV, (long)Nn * KV,
        Hh, 1, 0, 0, 1.f);

    long outOff = 0;
    for (int i = 0; i < 4; ++i) {
        const int C = Cs[i];
        const int ctiles = (C + TBN - 1) / TBN;

        // Q[b,h] = emb_i[b] @ Wq_i[h]^T : [1024, C]
        gemm_nt<<<dim3(ctiles, 8, Bb * Hh), blk>>>(
            emb[i], Wq[i], pQ, Nn, C, C,
            (long)Nn * C, 0, 0, (long)C * C, (long)Nn * C,
            Hh, 1, 0, 0, 1.f);

        // scores[b,h] = Q[b,h]^T @ K[b,h] / sqrt(KV) : [C, 960]
        gemm_tn<<<dim3(8, ctiles, Bb * Hh), blk>>>(
            pQ, pK, pS, C, KV, Nn,
            (long)Nn * C, (long)Nn * KV, (long)C * KV, sscale);

        // instance-norm stats per (b,h)
        stats_kernel<<<Bb * Hh, 512>>>(pS, pSt, C);

        // softmax over KV per row (b,h,c), in place
        softmax_kernel<<<Bb * Hh * C, 256>>>(pS, pSt, C);

        // ctx[b,n,c] = 1/H * sum_h V[b,h,n,:] . probs[b,h,c,:]
        gemm_nt<<<dim3(ctiles, 8, Bb), blk>>>(
            pV, pS, pC, Nn, C, KV,
            (long)Hh * Nn * KV, 0, (long)Hh * C * KV, 0, (long)Nn * C,
            1, Hh, (long)Nn * KV, (long)C * KV, 1.f / (float)Hh);

        // out[b,n,o] = ctx[b,n,:] . Wo[o,:]
        gemm_nt<<<dim3(ctiles, 8, Bb), blk>>>(
            pC, Wo[i], out + outOff, Nn, C, C,
            (long)Nn * C, 0, 0, 0, (long)Nn * C,
            1, 1, 0, 0, 1.f);

        outOff += (long)Bb * Nn * C;
    }
}

// round 5
// speedup vs baseline: 2.8173x; 2.8173x over previous
#include <cuda_runtime.h>
#include <cuda_bf16.h>
#include <math.h>
#include <stdint.h>

namespace {
constexpr int Bb = 8;
constexpr int Hh = 4;
constexpr int Nn = 1024;
constexpr int KV = 960;
constexpr int CMAX = 512;
}

// ---------------------------------------------------------------------------
// Scratch (static device globals — allocation-free per harness rules)
// ---------------------------------------------------------------------------
__device__ float g_Kt[(size_t)Bb * Hh * KV * Nn];    // [b,h,kv,n]
__device__ float g_V [(size_t)Bb * Hh * Nn * KV];    // [b,h,n,kv]
__device__ float g_Qt[(size_t)Bb * Hh * CMAX * Nn];  // [b,h,c,n]
__device__ float g_S [(size_t)Bb * Hh * CMAX * KV];  // [b,h,c,kv]
__device__ float g_ctx[(size_t)Bb * Nn * CMAX];      // [b,n,c]
__device__ float g_stats[Bb * Hh * 2];

__device__ __forceinline__ uint32_t smem_u32(const void* p) {
    uint32_t a;
    asm("{ .reg .u64 t; cvta.to.shared.u64 t, %1; cvt.u32.u64 %0, t; }" : "=r"(a) : "l"(p));
    return a;
}

#define SWZ64(o) ((o) ^ (((o) >> 3) & 0x30u))

#define LDMX4(r, addr)                                                          \
    asm volatile("ldmatrix.sync.aligned.m8n8.x4.shared.b16 {%0,%1,%2,%3}, [%4];" \
        : "=r"((r)[0]), "=r"((r)[1]), "=r"((r)[2]), "=r"((r)[3]) : "r"(addr))
#define LDMX2(r, addr)                                                          \
    asm volatile("ldmatrix.sync.aligned.m8n8.x2.shared.b16 {%0,%1}, [%2];"      \
        : "=r"((r)[0]), "=r"((r)[1]) : "r"(addr))
#define MMA16816(d, a, b)                                                       \
    asm volatile("mma.sync.aligned.m16n8k16.row.col.f32.bf16.bf16.f32 "         \
        "{%0,%1,%2,%3}, {%4,%5,%6,%7}, {%8,%9}, {%0,%1,%2,%3};"                 \
        : "+f"((d)[0]), "+f"((d)[1]), "+f"((d)[2]), "+f"((d)[3])                \
        : "r"((a)[0]), "r"((a)[1]), "r"((a)[2]), "r"((a)[3]),                   \
          "r"((b)[0]), "r"((b)[1]))

// ---------------------------------------------------------------------------
// NT GEMM via mma.sync bf16 hi/lo split (fp32-accurate).
// C[z][m][n] = scale * sum_h sum_k A_h[m][k] * B_h[n][k]
// M-tile 128, N-tile NT; K staged 32 fp32 per chunk.
// ---------------------------------------------------------------------------
template<int NT>
__global__ __launch_bounds__(256)
void gemm_mma(const float* __restrict__ A, const float* __restrict__ B,
              float* __restrict__ C,
              int M, int N, int K,
              long sAo, long sAi, long sBo, long sBi, long sC,
              int hDiv, int nAcc, long accA, long accB, float scale)
{
    constexpr int NLD = (128 + NT) * 8 / 256;   // float4 loads per thread per chunk
    constexpr int NN  = NT / 32;                // n-tiles (of 8) per warp
    constexpr int SM_BYTES = 128 * 64 * 2 + NT * 64 * 2;

    __shared__ __align__(128) char sm[SM_BYTES];
    const uint32_t su  = smem_u32(sm);
    const uint32_t aHi = su;
    const uint32_t aLo = su + 8192;
    const uint32_t bHi = su + 16384;
    const uint32_t bLo = su + 16384 + NT * 64;

    const int tid  = threadIdx.x;
    const int lane = tid & 31;
    const int wid  = tid >> 5;
    const int wm   = (wid >> 2) * 64;          // warp M offset (2 rows of warps)
    const int wn   = (wid & 3) * (NT / 4);     // warp N offset (4 cols of warps)

    const int m0 = blockIdx.y * 128;
    const int n0 = blockIdx.x * NT;
    const int z  = blockIdx.z;

    const float* Abase = A + (long)(z / hDiv) * sAo + (long)(z % hDiv) * sAi;
    const float* Bbase = B + (long)(z / hDiv) * sBo + (long)(z % hDiv) * sBi;
    float* Cp = C + (long)z * sC;
    const int mRem = M - m0;

    // per-lane ldmatrix row/k-slab components
    const int aRow  = (lane & 7) + ((lane >> 3) & 1) * 8;  // row within m16
    const int aSlab = (lane >> 4) * 16;                    // k-byte slab (0/16)
    const int bRow  = (lane & 7);
    const int bSlab = ((lane >> 3) & 1) * 16;

    float acc[4][NN][4];
#pragma unroll
    for (int i = 0; i < 4; i++)
#pragma unroll
        for (int j = 0; j < NN; j++)
#pragma unroll
            for (int r = 0; r < 4; r++) acc[i][j][r] = 0.f;

    const int kChunks = K >> 5;                 // K / 32
    const int nChunks = nAcc * kChunks;

    float4 v[NLD];

    // ---- prologue: LDG chunk 0 ----
    {
        const float* Ah = Abase;
        const float* Bh = Bbase;
#pragma unroll
        for (int j = 0; j < NLD; ++j) {
            const int idx = tid + j * 256;
            const int row = idx >> 3;
            const int q   = idx & 7;
            v[j] = make_float4(0.f, 0.f, 0.f, 0.f);
            if (row < 128) {
                if (row < mRem)
                    v[j] = *reinterpret_cast<const float4*>(Ah + (long)(m0 + row) * K + q * 4);
            } else {
                const int rl = row - 128;
                if (n0 + rl < N)
                    v[j] = *reinterpret_cast<const float4*>(Bh + (long)(n0 + rl) * K + q * 4);
            }
        }
    }

    for (int c = 0; c < nChunks; ++c) {
        // ---- STS: convert fp32 -> bf16 hi/lo, swizzled ----
#pragma unroll
        for (int j = 0; j < NLD; ++j) {
            const int idx = tid + j * 256;
            const int row = idx >> 3;
            const int q   = idx & 7;
            const int rl  = (row < 128) ? row : row - 128;
            const uint32_t pH = (row < 128) ? aHi : bHi;
            const uint32_t pL = (row < 128) ? aLo : bLo;
            uint32_t h01, h23, l01, l23;
            asm("cvt.rn.bf16x2.f32 %0, %1, %2;" : "=r"(h01) : "f"(v[j].y), "f"(v[j].x));
            asm("cvt.rn.bf16x2.f32 %0, %1, %2;" : "=r"(h23) : "f"(v[j].w), "f"(v[j].z));
            const float hx = __uint_as_float(h01 << 16);
            const float hy = __uint_as_float(h01 & 0xffff0000u);
            const float hz = __uint_as_float(h23 << 16);
            const float hw = __uint_as_float(h23 & 0xffff0000u);
            asm("cvt.rn.bf16x2.f32 %0, %1, %2;" : "=r"(l01) : "f"(v[j].y - hy), "f"(v[j].x - hx));
            asm("cvt.rn.bf16x2.f32 %0, %1, %2;" : "=r"(l23) : "f"(v[j].w - hw), "f"(v[j].z - hz));
            const uint32_t off = (uint32_t)rl * 64u + (uint32_t)q * 8u;
            const uint32_t sw  = SWZ64(off);
            asm volatile("st.shared.v2.b32 [%0], {%1,%2};" :: "r"(pH + sw), "r"(h01), "r"(h23) : "memory");
            asm volatile("st.shared.v2.b32 [%0], {%1,%2};" :: "r"(pL + sw), "r"(l01), "r"(l23) : "memory");
        }
        __syncthreads();

        // ---- prefetch next chunk into registers ----
        if (c + 1 < nChunks) {
            const int cn = c + 1;
            const int hn = cn / kChunks;
            const int k0 = (cn % kChunks) << 5;
            const float* Ah = Abase + (long)hn * accA;
            const float* Bh = Bbase + (long)hn * accB;
#pragma unroll
            for (int j = 0; j < NLD; ++j) {
                const int idx = tid + j * 256;
                const int row = idx >> 3;
                const int q   = idx & 7;
                v[j] = make_float4(0.f, 0.f, 0.f, 0.f);
                if (row < 128) {
                    if (row < mRem)
                        v[j] = *reinterpret_cast<const float4*>(Ah + (long)(m0 + row) * K + k0 + q * 4);
                } else {
                    const int rl = row - 128;
                    if (n0 + rl < N)
                        v[j] = *reinterpret_cast<const float4*>(Bh + (long)(n0 + rl) * K + k0 + q * 4);
                }
            }
        }

        // ---- compute: 2 k-steps of 16 ----
#pragma unroll
        for (int ks = 0; ks < 2; ++ks) {
            const uint32_t ksb = (uint32_t)ks * 32u;
            uint32_t ah[4][4], al[4][4];
#pragma unroll
            for (int mt = 0; mt < 4; ++mt) {
                const uint32_t off = (uint32_t)(wm + mt * 16 + aRow) * 64u + ksb + (uint32_t)aSlab;
                const uint32_t sw  = SWZ64(off);
                LDMX4(ah[mt], aHi + sw);
                LDMX4(al[mt], aLo + sw);
            }
            uint32_t bh[NN][2], bl[NN][2];
#pragma unroll
            for (int nt = 0; nt < NN; ++nt) {
                const uint32_t off = (uint32_t)(wn + nt * 8 + bRow) * 64u + ksb + (uint32_t)bSlab;
                const uint32_t sw  = SWZ64(off);
                LDMX2(bh[nt], bHi + sw);
                LDMX2(bl[nt], bLo + sw);
            }
#pragma unroll
            for (int mt = 0; mt < 4; ++mt)
#pragma unroll
                for (int nt = 0; nt < NN; ++nt) {
                    MMA16816(acc[mt][nt], ah[mt], bh[nt]);
                    MMA16816(acc[mt][nt], ah[mt], bl[nt]);
                    MMA16816(acc[mt][nt], al[mt], bh[nt]);
                }
        }
        __syncthreads();
    }

    // ---- epilogue ----
#pragma unroll
    for (int mt = 0; mt < 4; ++mt) {
#pragma unroll
        for (int nt = 0; nt < NN; ++nt) {
            const int m1 = m0 + wm + mt * 16 + (lane >> 2);
            const int n  = n0 + wn + nt * 8 + (lane & 3) * 2;
            if (n < N) {
                if (m1 < M) {
                    float2 o = make_float2(acc[mt][nt][0] * scale, acc[mt][nt][1] * scale);
                    *reinterpret_cast<float2*>(Cp + (long)m1 * N + n) = o;
                }
                const int m2 = m1 + 8;
                if (m2 < M) {
                    float2 o = make_float2(acc[mt][nt][2] * scale, acc[mt][nt][3] * scale);
                    *reinterpret_cast<float2*>(Cp + (long)m2 * N + n) = o;
                }
            }
        }
    }
}

// ---------------------------------------------------------------------------
// Instance-norm statistics + softmax (unchanged, verified)
// ---------------------------------------------------------------------------
__inline__ __device__ float warpSum(float v) {
#pragma unroll
    for (int o = 16; o; o >>= 1) v += __shfl_xor_sync(0xffffffffu, v, o);
    return v;
}
__inline__ __device__ float warpMax(float v) {
#pragma unroll
    for (int o = 16; o; o >>= 1) v = fmaxf(v, __shfl_xor_sync(0xffffffffu, v, o));
    return v;
}

__global__ void stats_kernel(const float* __restrict__ S, float* __restrict__ stats, int C)
{
    const int z = blockIdx.x;
    const long n = (long)C * KV;
    const float* p = S + (long)z * n;
    float s = 0.f, sq = 0.f;
    for (long i = threadIdx.x; i < n; i += blockDim.x) {
        const float x = p[i];
        s += x;
        sq += x * x;
    }
    __shared__ float sh1[16], sh2[16];
    s = warpSum(s);
    sq = warpSum(sq);
    const int w = threadIdx.x >> 5, l = threadIdx.x & 31;
    if (l == 0) { sh1[w] = s; sh2[w] = sq; }
    __syncthreads();
    if (w == 0) {
        s  = (l < 16) ? sh1[l] : 0.f;
        sq = (l < 16) ? sh2[l] : 0.f;
        s = warpSum(s);
        sq = warpSum(sq);
        if (l == 0) {
            const float invn = 1.f / (float)n;
            const float mean = s * invn;
            const float var  = sq * invn - mean * mean;
            stats[z * 2 + 0] = mean;
            stats[z * 2 + 1] = rsqrtf(var + 1e-5f);
        }
    }
}

__global__ void softmax_kernel(float* __restrict__ S, const float* __restrict__ stats, int C)
{
    const int row = blockIdx.x;
    const int z = row / C;
    const float inv = stats[z * 2 + 1];
    float* p = S + (long)row * KV;
    const int tid = threadIdx.x;
    const int w = tid >> 5, l = tid & 31;

    __shared__ float sred[8];
    __shared__ float s_mx, s_se;

    float mx = -1e30f;
    for (int i = tid; i < KV; i += 256) mx = fmaxf(mx, p[i]);
    mx = warpMax(mx);
    if (l == 0) sred[w] = mx;
    __syncthreads();
    if (tid == 0) {
        float m = sred[0];
#pragma unroll
        for (int i = 1; i < 8; i++) m = fmaxf(m, sred[i]);
        s_mx = m;
    }
    __syncthreads();
    mx = s_mx;

    float se = 0.f;
    for (int i = tid; i < KV; i += 256) {
        const float e = expf((p[i] - mx) * inv);
        p[i] = e;
        se += e;
    }
    se = warpSum(se);
    __syncthreads();
    if (l == 0) sred[w] = se;
    __syncthreads();
    if (tid == 0) {
        float t = 0.f;
#pragma unroll
        for (int i = 0; i < 8; i++) t += sred[i];
        s_se = 1.f / t;
    }
    __syncthreads();
    const float r = s_se;
    for (int i = tid; i < KV; i += 256) p[i] *= r;
}

// ---------------------------------------------------------------------------
// Host launch
// ---------------------------------------------------------------------------
static inline void launch_gemm(int NT, dim3 grid,
                               const float* A, const float* B, float* C,
                               int M, int N, int K,
                               long sAo, long sAi, long sBo, long sBi, long sC,
                               int hDiv, int nAcc, long accA, long accB, float scale)
{
    if (NT == 128) {
        gemm_mma<128><<<grid, 256>>>(A, B, C, M, N, K, sAo, sAi, sBo, sBi, sC,
                                     hDiv, nAcc, accA, accB, scale);
    } else {
        gemm_mma<64><<<grid, 256>>>(A, B, C, M, N, K, sAo, sAi, sBo, sBi, sC,
                                    hDiv, nAcc, accA, accB, scale);
    }
}

extern "C" void kernel_launch(void* const* d_in, const int* in_sizes, int n_in,
                              void* d_out, int out_size)
{
    (void)n_in; (void)out_size;

    // ---- input-order detection (dict order has Wq/Wo interleaved) ----
    int ie[4], ieall, iwq[4], iwo[4], iwk, iwv;
    const int SZ_WK   = 4 * 960 * 960;
    const int SZ_EMB1 = 8 * 1024 * 64;
    const int SZ_WO1  = 64 * 64;

    if (in_sizes[0] == SZ_WK) {
        iwk = 0;
        iwo[0] = 1; iwo[1] = 2; iwo[2] = 3; iwo[3] = 4;
        iwq[0] = 5; iwq[1] = 6; iwq[2] = 7; iwq[3] = 8;
        iwv = 9;
        ie[0] = 10; ie[1] = 11; ie[2] = 12; ie[3] = 13;
        ieall = 14;
    } else if (in_sizes[0] == SZ_EMB1 && in_sizes[5] == SZ_WK) {
        ie[0] = 0; ie[1] = 1; ie[2] = 2; ie[3] = 3; ieall = 4;
        iwk = 5;
        iwo[0] = 6; iwo[1] = 7; iwo[2] = 8; iwo[3] = 9;
        iwq[0] = 10; iwq[1] = 11; iwq[2] = 12; iwq[3] = 13;
        iwv = 14;
    } else if (in_sizes[6] == SZ_WO1) {
        // dict insertion order (INTERLEAVED): emb1..4, emb_all, Wq1,Wo1,...,Wk,Wv
        ie[0] = 0; ie[1] = 1; ie[2] = 2; ie[3] = 3; ieall = 4;
        iwq[0] = 5;  iwo[0] = 6;
        iwq[1] = 7;  iwo[1] = 8;
        iwq[2] = 9;  iwo[2] = 10;
        iwq[3] = 11; iwo[3] = 12;
        iwk = 13; iwv = 14;
    } else {
        ie[0] = 0; ie[1] = 1; ie[2] = 2; ie[3] = 3; ieall = 4;
        iwq[0] = 5; iwq[1] = 6; iwq[2] = 7; iwq[3] = 8;
        iwo[0] = 9; iwo[1] = 10; iwo[2] = 11; iwo[3] = 12;
        iwk = 13; iwv = 14;
    }

    const float* emb[4]  = {(const float*)d_in[ie[0]], (const float*)d_in[ie[1]],
                            (const float*)d_in[ie[2]], (const float*)d_in[ie[3]]};
    const float* emb_all = (const float*)d_in[ieall];
    const float* Wq[4]   = {(const float*)d_in[iwq[0]], (const float*)d_in[iwq[1]],
                            (const float*)d_in[iwq[2]], (const float*)d_in[iwq[3]]};
    const float* Wo[4]   = {(const float*)d_in[iwo[0]], (const float*)d_in[iwo[1]],
                            (const float*)d_in[iwo[2]], (const float*)d_in[iwo[3]]};
    const float* Wk      = (const float*)d_in[iwk];
    const float* Wv      = (const float*)d_in[iwv];
    float* out = (float*)d_out;

    float *pKt, *pV, *pQt, *pS, *pC, *pSt;
    cudaGetSymbolAddress((void**)&pKt, g_Kt);
    cudaGetSymbolAddress((void**)&pV,  g_V);
    cudaGetSymbolAddress((void**)&pQt, g_Qt);
    cudaGetSymbolAddress((void**)&pS,  g_S);
    cudaGetSymbolAddress((void**)&pC,  g_ctx);
    cudaGetSymbolAddress((void**)&pSt, g_stats);

    const int Cs[4] = {64, 128, 256, 512};
    const float sscale = 0.032274861f;  // 1/sqrt(960)

    // 1) Kt[z][kv][n] = sum_k Wk[h][kv][k] * emb_all[b][n][k]   (M=960, N=1024, K=960)
    launch_gemm(128, dim3(8, 8, Bb * Hh),
                Wk, emb_all, pKt, KV, Nn, KV,
                0, (long)KV * KV, (long)Nn * KV, 0, (long)KV * Nn,
                Hh, 1, 0, 0, 1.f);

    // 2) V[z][n][kv] = sum_k emb_all[b][n][k] * Wv[h][kv][k]    (M=1024, N=960, K=960)
    launch_gemm(128, dim3(8, 8, Bb * Hh),
                emb_all, Wv, pV, Nn, KV, KV,
                (long)Nn * KV, 0, 0, (long)KV * KV, (long)Nn * KV,
                Hh, 1, 0, 0, 1.f);

    long outOff = 0;
    for (int i = 0; i < 4; ++i) {
        const int C = Cs[i];
        const int mtC = (C + 127) / 128;
        const int NTC = (C >= 128) ? 128 : 64;
        const int ntC = (C + NTC - 1) / NTC;

        // 3) Qt[z][c][n] = sum_k Wq_i[h][c][k] * emb_i[b][n][k]  (M=C, N=1024, K=C)
        launch_gemm(128, dim3(8, mtC, Bb * Hh),
                    Wq[i], emb[i], pQt, C, Nn, C,
                    0, (long)C * C, (long)Nn * C, 0, (long)C * Nn,
                    Hh, 1, 0, 0, 1.f);

        // 4) S[z][c][kv] = sscale * sum_n Qt[z][c][n] * Kt[z][kv][n]  (M=C, N=960, K=1024)
        launch_gemm(128, dim3(8, mtC, Bb * Hh),
                    pQt, pKt, pS, C, KV, Nn,
                    (long)C * Nn, 0, (long)KV * Nn, 0, (long)C * KV,
                    1, 1, 0, 0, sscale);

        // instance-norm stats per (b,h)
        stats_kernel<<<Bb * Hh, 512>>>(pS, pSt, C);

        // softmax over KV per row, in place
        softmax_kernel<<<Bb * Hh * C, 256>>>(pS, pSt, C);

        // 5) ctx[b][n][c] = 0.25 * sum_h sum_kv V[b,h][n][kv] * probs[b,h][c][kv]
        launch_gemm(NTC, dim3(ntC, 8, Bb),
                    pV, pS, pC, Nn, C, KV,
                    (long)Hh * Nn * KV, 0, (long)Hh * C * KV, 0, (long)Nn * C,
                    1, Hh, (long)Nn * KV, (long)C * KV, 0.25f);

        // 6) out[b][n][o] = sum_c ctx[b][n][c] * Wo_i[o][c]   (M=1024, N=C, K=C)
        launch_gemm(NTC, dim3(ntC, 8, Bb),
                    pC, Wo[i], out + outOff, Nn, C, C,
                    (long)Nn * C, 0, 0, 0, (long)Nn * C,
                    1, 1, 0, 0, 1.f);

        outOff += (long)Bb * Nn * C;
    }
}